// round 15
// baseline (speedup 1.0000x reference)
#include <cuda_runtime.h>
#include <math.h>

#define NRES 768
#define MSAD 384
#define NH 12
#define PAIRD 128
#define OUTD 384
#define PROJ 1152
#define FINALD 2112

typedef unsigned long long ull;

// ---------------- f32x2 helpers (Blackwell packed fp32) ---------------------
__device__ __forceinline__ ull pk2(float v) {
    ull r; asm("mov.b64 %0, {%1, %1};" : "=l"(r) : "f"(v)); return r;
}
__device__ __forceinline__ ull pk2two(float lo, float hi) {
    ull r; asm("mov.b64 %0, {%1, %2};" : "=l"(r) : "f"(lo), "f"(hi)); return r;
}
__device__ __forceinline__ void fma2(ull& d, ull a, ull b) {
    asm("fma.rn.f32x2 %0, %1, %2, %0;" : "+l"(d) : "l"(a), "l"(b));
}
__device__ __forceinline__ void add2(ull& d, ull b) {
    asm("add.rn.f32x2 %0, %0, %1;" : "+l"(d) : "l"(b));
}
__device__ __forceinline__ void mul2(ull& d, ull b) {
    asm("mul.rn.f32x2 %0, %0, %1;" : "+l"(d) : "l"(b));
}
__device__ __forceinline__ float2 upk(ull v) {
    float2 r; asm("mov.b64 {%0, %1}, %2;" : "=f"(r.x), "=f"(r.y) : "l"(v)); return r;
}
// ---------------- cp.async helpers ------------------------------------------
__device__ __forceinline__ void cp16(void* dst, const void* src) {
    unsigned d = (unsigned)__cvta_generic_to_shared(dst);
    asm volatile("cp.async.cg.shared.global [%0], [%1], 16;" :: "r"(d), "l"(src));
}
__device__ __forceinline__ void cp_commit() {
    asm volatile("cp.async.commit_group;" ::: "memory");
}
__device__ __forceinline__ void cp_wait2() {
    asm volatile("cp.async.wait_group 2;" ::: "memory");
}

// ---------------- scratch (device globals; no allocation allowed) ----------
__device__ float g_proj[NRES * PROJ];
__device__ float g_qpack[NH * NRES * 28];
__device__ float g_kpackT[NH * 32 * NRES];  // [h][d][j], d-major (d28 = bias)
__device__ float g_vpack2[NH * NRES * 40];
__device__ float g_logits[NH * NRES * NRES]; // raw qk -> raw full logits -> attn
__device__ float g_final[NRES * FINALD];
__device__ float g_part[3][NRES * OUTD];
__device__ float g_aovp[2][NRES * 1536];     // unnormalized j-half partials
__device__ float g_mz[2 * NRES * 24];        // per (jh,i,h): m, Z
__device__ float g_MZ[NRES * 24];            // per (i,h): M, 1/Z

// ---------------- K1a: projection GEMM 768x1152x384 (f32x2) -----------------
__global__ __launch_bounds__(256) void k1a_gemm(const float* __restrict__ in1d,
                                                const float* __restrict__ qw,  const float* __restrict__ qb,
                                                const float* __restrict__ kvw, const float* __restrict__ kvb,
                                                const float* __restrict__ qpw, const float* __restrict__ qpb,
                                                const float* __restrict__ kvpw,const float* __restrict__ kvpb) {
    __shared__ float sA[32][65];
    __shared__ ull sB2[32][32];
    int tid = threadIdx.x;
    int tx = tid & 15, ty = tid >> 4;
    int m0 = blockIdx.y * 64, n0 = blockIdx.x * 64;
    ull acc[4][2] = {};
    for (int k0 = 0; k0 < MSAD; k0 += 32) {
        for (int idx = tid; idx < 64 * 32; idx += 256) {
            int m = idx >> 5, kk = idx & 31;
            sA[kk][m] = in1d[(m0 + m) * MSAD + k0 + kk];
        }
        for (int idx = tid; idx < 32 * 32; idx += 256) {
            int kk = idx >> 5, op = idx & 31;
            int o = n0 + op * 2, k = k0 + kk;
            float2 w;
            if (o < 192)      w = *(const float2*)(qw + k * 192 + o);
            else if (o < 576) w = *(const float2*)(kvw + k * 384 + (o - 192));
            else if (o < 720) w = *(const float2*)(qpw + k * 144 + (o - 576));
            else              w = *(const float2*)(kvpw + k * 432 + (o - 720));
            sB2[kk][op] = pk2two(w.x, w.y);
        }
        __syncthreads();
#pragma unroll
        for (int kk = 0; kk < 32; kk++) {
            ulonglong2 b01 = *(const ulonglong2*)&sB2[kk][tx * 2];
#pragma unroll
            for (int r = 0; r < 4; r++) {
                ull a2 = pk2(sA[kk][ty * 4 + r]);
                fma2(acc[r][0], a2, b01.x);
                fma2(acc[r][1], a2, b01.y);
            }
        }
        __syncthreads();
    }
#pragma unroll
    for (int r = 0; r < 4; r++) {
        int m = m0 + ty * 4 + r, o = n0 + tx * 4;
        float2 lo = upk(acc[r][0]), hi = upk(acc[r][1]);
        float vv[4] = { lo.x, lo.y, hi.x, hi.y };
#pragma unroll
        for (int q = 0; q < 4; q++) {
            int oo = o + q;
            float b;
            if (oo < 192)      b = qb[oo];
            else if (oo < 576) b = kvb[oo - 192];
            else if (oo < 720) b = qpb[oo - 576];
            else               b = kvpb[oo - 720];
            g_proj[(size_t)m * PROJ + oo] = vv[q] + b;
        }
    }
}

// ---------------- K1b: apply rotations, pack q/k/v --------------------------
__global__ __launch_bounds__(256) void k1b_pack(const float* __restrict__ rot,
                                                const float* __restrict__ trans,
                                                const float* __restrict__ tpw) {
    __shared__ float sp[PROJ];
    __shared__ float srot[9], strans[3], spw[12];
    __shared__ float sg[192 * 3];
    int n = blockIdx.x, tid = threadIdx.x;
    for (int t = tid; t < PROJ; t += 256) sp[t] = g_proj[n * PROJ + t];
    if (tid < 9) srot[tid] = rot[n * 9 + tid];
    if (tid < 3) strans[tid] = trans[n * 3 + tid];
    if (tid < 12) {
        float x = tpw[tid];
        float sf = (x > 20.f) ? x : log1pf(__expf(x));
        spw[tid] = sf * 0.13608276348795434f; // sqrt(1/54)
    }
    __syncthreads();

    if (tid < 192) {
        int h = tid >> 4, d = tid & 15;
        g_qpack[(h * NRES + n) * 28 + d] = sp[tid] * 0.14433756729740643f; // 1/sqrt(48)
    }
    for (int t = tid; t < 384; t += 256) {
        int h = t >> 5, d = t & 31;
        if (d < 16) g_kpackT[((size_t)h * 32 + d) * NRES + n] = sp[192 + t];
        else        g_vpack2[((size_t)h * NRES + n) * 40 + (d - 16)] = sp[192 + t];
    }
    if (tid < 192) {
        float l0, l1, l2;
        if (tid < 48) { l0 = sp[576 + tid]; l1 = sp[576 + 48 + tid]; l2 = sp[576 + 96 + tid]; }
        else { int vs = tid - 48; l0 = sp[720 + vs]; l1 = sp[720 + 144 + vs]; l2 = sp[720 + 288 + vs]; }
#pragma unroll
        for (int c = 0; c < 3; c++)
            sg[tid * 3 + c] = srot[c * 3 + 0] * l0 + srot[c * 3 + 1] * l1 + srot[c * 3 + 2] * l2 + strans[c];
    }
    __syncthreads();
    if (tid < 48) {
        int h = tid >> 2, p = tid & 3;
        float pw = spw[h];
#pragma unroll
        for (int c = 0; c < 3; c++)
            g_qpack[(h * NRES + n) * 28 + 16 + p * 3 + c] = pw * sg[tid * 3 + c];
    } else if (tid < 192) {
        int vs = tid - 48, h = vs / 12, s = vs % 12;
        if (s < 4) {
#pragma unroll
            for (int c = 0; c < 3; c++)
                g_kpackT[((size_t)h * 32 + 16 + s * 3 + c) * NRES + n] = sg[tid * 3 + c];
        } else {
#pragma unroll
            for (int c = 0; c < 3; c++)
                g_vpack2[((size_t)h * NRES + n) * 40 + 16 + (s - 4) * 3 + c] = sg[tid * 3 + c];
        }
    }
    if (tid >= 192 && tid < 204) {
        int h = tid - 192;
        float s2 = 0.f;
        for (int s = 0; s < 4; s++)
            for (int c = 0; c < 3; c++) {
                float v = sg[(48 + h * 12 + s) * 3 + c];
                s2 += v * v;
            }
        g_kpackT[((size_t)h * 32 + 28) * NRES + n] = -0.5f * spw[h] * s2;
    }
}

// ---------------- K3qk: raw qk scalar+point logits -> g_logits --------------
__global__ __launch_bounds__(256) void k3_qk() {
    __shared__ ull su2[8][14];
    int h = blockIdx.y, i0 = blockIdx.x * 8;
    int tid = threadIdx.x;
    for (int t = tid; t < 8 * 14; t += 256) {
        int i8 = t / 14, dp = t % 14;
        const float* qp = g_qpack + ((size_t)h * NRES + (i0 + i8)) * 28 + dp * 2;
        su2[i8][dp] = pk2two(qp[0], qp[1]);
    }
    __syncthreads();
    const float* kbase = g_kpackT + (size_t)h * 32 * NRES;
    for (int jj = 0; jj < 3; jj++) {
        int j = jj * 256 + tid;
        const float* kb = kbase + j;
        ull wr2[14];
#pragma unroll
        for (int dp = 0; dp < 14; dp++)
            wr2[dp] = pk2two(__ldg(kb + (size_t)(2 * dp) * NRES),
                             __ldg(kb + (size_t)(2 * dp + 1) * NRES));
        float bias = __ldg(kb + (size_t)28 * NRES);
#pragma unroll
        for (int i8 = 0; i8 < 8; i8++) {
            ull acc2 = 0;
#pragma unroll
            for (int dp = 0; dp < 14; dp++) fma2(acc2, su2[i8][dp], wr2[dp]);
            float2 t = upk(acc2);
            g_logits[((size_t)h * NRES + (i0 + i8)) * NRES + j] = t.x + t.y + bias;
        }
    }
}

// ---------------- kfu: fused a2d + logits + ONLINE softmax + a_over_2d ------
// Block = (i, jh). One in2d read. Writes raw logits + unnormalized partials.
// smem layout (bytes):
//   sqk  float[384*12]  @0      (18432)
//   sbuf float[3*2112]  @18432  (25344)   stage = 16 rows x 132 pitch
//   sw2  ull[768]       @43776  (6144)
//   sl   float[192]     @49920  (768)
//   se   float[192]     @50688  (768)
//   sx   ull[96]        @51456  (768)
//   sb   float[12]      @52224  (48)
//   smr  float[12]      @52272  (48)
//   ssc  float[12]      @52320  (48)
//   sZ   float[12]      @52368  (48)
#define KFU_SMEM 52416
__global__ __launch_bounds__(256) void kfu(const float* __restrict__ in2d,
                                           const float* __restrict__ w2d,
                                           const float* __restrict__ b2d) {
    extern __shared__ char smraw[];
    float* sqk = (float*)smraw;
    float* sbuf = (float*)(smraw + 18432);
    ull*   sw2 = (ull*)(smraw + 43776);
    float* sl  = (float*)(smraw + 49920);
    float* se  = (float*)(smraw + 50688);
    ull*   sx  = (ull*)(smraw + 51456);
    float* sb  = (float*)(smraw + 52224);
    float* smr = (float*)(smraw + 52272);
    float* ssc = (float*)(smraw + 52320);
    float* sZ  = (float*)(smraw + 52368);

    int i = blockIdx.x >> 1, jh = blockIdx.x & 1;
    int tid = threadIdx.x;
    const float* src = in2d + ((size_t)i * NRES + jh * 384) * PAIRD;

    // prologue: issue chunks 0, 1
#pragma unroll
    for (int s = 0; s < 2; s++) {
#pragma unroll
        for (int t = 0; t < 2; t++) {
            int f = tid + t * 256;
            int r = f >> 5, c4 = f & 31;
            cp16(sbuf + s * 2112 + r * 132 + c4 * 4,
                 src + (size_t)(s * 16 + r) * PAIRD + c4 * 4);
        }
        cp_commit();
    }
    // stage qk (transposed), weights, init state — overlaps with cp.async
    for (int f = tid; f < 4608; f += 256) {
        int h = f / 384, jl = f % 384;
        sqk[jl * 12 + h] = __ldg(g_logits + ((size_t)h * NRES + i) * NRES + jh * 384 + jl);
    }
    for (int f = tid; f < 768; f += 256) {
        int c = f / 6, hp = f % 6;
        float2 w = *(const float2*)(w2d + c * 12 + hp * 2);
        sw2[f] = pk2two(w.x, w.y);
    }
    if (tid < 12) {
        sb[tid] = b2d[tid];
        smr[tid] = -1e30f;
        sZ[tid] = 0.f;
    }
    __syncthreads();

    int rg = tid >> 6, cp = tid & 63;
    int jl_a = tid / 12, sub = tid % 12;
    int hp_a = sub >> 1, ch = sub & 1;
    bool act = tid < 192;
    ull acc[12] = {};

    for (int s = 0; s < 24; s++) {
        if (s + 2 < 24) {
            int sn = s + 2;
#pragma unroll
            for (int t = 0; t < 2; t++) {
                int f = tid + t * 256;
                int r = f >> 5, c4 = f & 31;
                cp16(sbuf + (sn % 3) * 2112 + r * 132 + c4 * 4,
                     src + (size_t)(sn * 16 + r) * PAIRD + c4 * 4);
            }
        }
        cp_commit();
        cp_wait2();
        __syncthreads();
        const float* row = sbuf + (s % 3) * 2112;

        // a2d partial: thread (jl_a, hp_a, ch) covers 64 columns
        ull part = 0;
        if (act) {
            const float4* p4 = (const float4*)(row + jl_a * 132 + ch * 64);
#pragma unroll
            for (int k4 = 0; k4 < 16; k4++) {
                float4 a = p4[k4];
                int c0 = ch * 64 + k4 * 4;
                fma2(part, pk2(a.x), sw2[(c0 + 0) * 6 + hp_a]);
                fma2(part, pk2(a.y), sw2[(c0 + 1) * 6 + hp_a]);
                fma2(part, pk2(a.z), sw2[(c0 + 2) * 6 + hp_a]);
                fma2(part, pk2(a.w), sw2[(c0 + 3) * 6 + hp_a]);
            }
            if (ch) sx[jl_a * 6 + hp_a] = part;
        }
        __syncthreads();
        if (act && !ch) {
            add2(part, sx[jl_a * 6 + hp_a]);
            float2 t2 = upk(part);
            int jloc = s * 16 + jl_a;       // j within half
            int h0 = 2 * hp_a;
            float l0 = sqk[jloc * 12 + h0]     + (t2.x + sb[h0])     * 0.5773502691896258f;
            float l1 = sqk[jloc * 12 + h0 + 1] + (t2.y + sb[h0 + 1]) * 0.5773502691896258f;
            sl[jl_a * 12 + h0] = l0;
            sl[jl_a * 12 + h0 + 1] = l1;
            size_t gj = (size_t)jh * 384 + jloc;
            g_logits[((size_t)h0 * NRES + i) * NRES + gj] = l0;
            g_logits[((size_t)(h0 + 1) * NRES + i) * NRES + gj] = l1;
        }
        __syncthreads();
        if (tid < 12) {
            float mc = -1e30f;
#pragma unroll
            for (int jl = 0; jl < 16; jl++) mc = fmaxf(mc, sl[jl * 12 + tid]);
            float mo = smr[tid];
            float mn = fmaxf(mo, mc);
            ssc[tid] = __expf(mo - mn);
            smr[tid] = mn;
        }
        __syncthreads();
        if (act) {
            se[jl_a * 12 + sub] = __expf(sl[jl_a * 12 + sub] - smr[sub]);
        }
        __syncthreads();
        if (tid < 12) {
            float zs = 0.f;
#pragma unroll
            for (int jl = 0; jl < 16; jl++) zs += se[jl * 12 + tid];
            sZ[tid] = sZ[tid] * ssc[tid] + zs;
        }
        // rescale + accumulate
#pragma unroll
        for (int h = 0; h < 12; h++) mul2(acc[h], pk2(ssc[h]));
        const ull* bb = (const ull*)row;
#pragma unroll
        for (int r = 0; r < 4; r++) {
            int jl = rg * 4 + r;
            ull d = bb[jl * 66 + cp];
            const float4* ap = (const float4*)&se[jl * 12];
            float4 a0 = ap[0], a1 = ap[1], a2v = ap[2];
            fma2(acc[0], pk2(a0.x), d);  fma2(acc[1], pk2(a0.y), d);
            fma2(acc[2], pk2(a0.z), d);  fma2(acc[3], pk2(a0.w), d);
            fma2(acc[4], pk2(a1.x), d);  fma2(acc[5], pk2(a1.y), d);
            fma2(acc[6], pk2(a1.z), d);  fma2(acc[7], pk2(a1.w), d);
            fma2(acc[8], pk2(a2v.x), d); fma2(acc[9], pk2(a2v.y), d);
            fma2(acc[10], pk2(a2v.z), d); fma2(acc[11], pk2(a2v.w), d);
        }
        __syncthreads();
    }
    // cross-rg reduction (reuse sbuf+sw2 region: 31488 B >= 26624)
    ull* red = (ull*)(smraw + 18432);
#pragma unroll
    for (int h = 0; h < 12; h++) red[(rg * 64 + cp) * 13 + h] = acc[h];
    __syncthreads();
    float* dstp = g_aovp[jh] + (size_t)i * 1536;
    for (int pi = tid; pi < 768; pi += 256) {
        int h = pi >> 6, c2 = pi & 63;
        ull t0 = red[(0 * 64 + c2) * 13 + h];
        add2(t0, red[(1 * 64 + c2) * 13 + h]);
        add2(t0, red[(2 * 64 + c2) * 13 + h]);
        add2(t0, red[(3 * 64 + c2) * 13 + h]);
        float2 v = upk(t0);
        *(float2*)(dstp + h * PAIRD + 2 * c2) = v;
    }
    if (tid < 12) {
        g_mz[((size_t)jh * NRES + i) * 24 + tid * 2]     = smr[tid];
        g_mz[((size_t)jh * NRES + i) * 24 + tid * 2 + 1] = sZ[tid];
    }
}

// ---------------- K4r: merge j-half partials (flash split-KV) ---------------
__global__ __launch_bounds__(256) void k4r_reduce() {
    __shared__ float swA[12], swB[12];
    int i = blockIdx.x, tid = threadIdx.x;
    if (tid < 12) {
        float m0 = g_mz[((size_t)0 * NRES + i) * 24 + tid * 2];
        float Z0 = g_mz[((size_t)0 * NRES + i) * 24 + tid * 2 + 1];
        float m1 = g_mz[((size_t)1 * NRES + i) * 24 + tid * 2];
        float Z1 = g_mz[((size_t)1 * NRES + i) * 24 + tid * 2 + 1];
        float M = fmaxf(m0, m1);
        float w0 = __expf(m0 - M), w1 = __expf(m1 - M);
        float zi = 1.f / (w0 * Z0 + w1 * Z1);
        swA[tid] = w0 * zi;
        swB[tid] = w1 * zi;
        g_MZ[(size_t)i * 24 + tid * 2] = M;
        g_MZ[(size_t)i * 24 + tid * 2 + 1] = zi;
    }
    __syncthreads();
    const float* p0 = g_aovp[0] + (size_t)i * 1536;
    const float* p1 = g_aovp[1] + (size_t)i * 1536;
    float* dst = g_final + (size_t)i * FINALD + 576;
    for (int x = tid; x < 1536; x += 256) {
        int h = x >> 7;
        dst[x] = p0[x] * swA[h] + p1[x] * swB[h];
    }
}

// ---------------- K3n: normalize raw logits -> attn (for k4b) ---------------
__global__ __launch_bounds__(256) void k3n_norm() {
    __shared__ float sM[8], sZi[8];
    int h = blockIdx.y, i0 = blockIdx.x * 8;
    int tid = threadIdx.x;
    if (tid < 8) {
        sM[tid]  = g_MZ[(size_t)(i0 + tid) * 24 + h * 2];
        sZi[tid] = g_MZ[(size_t)(i0 + tid) * 24 + h * 2 + 1];
    }
    __syncthreads();
#pragma unroll
    for (int jj = 0; jj < 3; jj++) {
        int j = jj * 256 + tid;
#pragma unroll
        for (int i8 = 0; i8 < 8; i8++) {
            size_t idx = ((size_t)h * NRES + i0 + i8) * NRES + j;
            float l = g_logits[idx];
            g_logits[idx] = __expf(l - sM[i8]) * sZi[i8];
        }
    }
}

// ---------------- K4b: per-head GEMM for v / vp + rotate-back epilogue ------
__global__ __launch_bounds__(320) void k4b_vattend(const float* __restrict__ rot,
                                                   const float* __restrict__ trans) {
    __shared__ float2 sattn2[64][65];
    __shared__ ull svp[64 * 20];
    __shared__ float srpg[64][24];
    int i0 = blockIdx.x * 64, h = blockIdx.y;
    int tid = threadIdx.x, il = tid & 63, dg = tid >> 6;
    ull acc[4] = {};
    for (int j0 = 0; j0 < NRES; j0 += 64) {
        for (int f = tid; f < 4096; f += 320) {
            int r = f >> 6, c = f & 63;
            float a = g_logits[((size_t)h * NRES + i0 + r) * NRES + j0 + c];
            sattn2[r][c] = make_float2(a, a);
        }
        for (int f = tid; f < 1280; f += 320)
            svp[f] = __ldg((const ull*)(g_vpack2 + ((size_t)h * NRES + j0) * 40) + f);
        __syncthreads();
#pragma unroll 4
        for (int jj = 0; jj < 64; jj++) {
            ull a2 = *(const ull*)&sattn2[il][jj];
            const ulonglong2* wv = (const ulonglong2*)&svp[jj * 20 + dg * 4];
            ulonglong2 w01 = wv[0], w23 = wv[1];
            fma2(acc[0], a2, w01.x); fma2(acc[1], a2, w01.y);
            fma2(acc[2], a2, w23.x); fma2(acc[3], a2, w23.y);
        }
        __syncthreads();
    }
    int n_i = i0 + il;
    float v[8];
#pragma unroll
    for (int q = 0; q < 4; q++) {
        float2 t = upk(acc[q]);
        v[2 * q] = t.x; v[2 * q + 1] = t.y;
    }
    if (dg < 2) {
        float* dst = g_final + (size_t)n_i * FINALD + h * 16 + dg * 8;
#pragma unroll
        for (int t = 0; t < 8; t++) dst[t] = v[t];
    } else {
        int d0 = (dg - 2) * 8;
#pragma unroll
        for (int t = 0; t < 8; t++) srpg[il][d0 + t] = v[t];
    }
    __syncthreads();
    for (int f = tid; f < 512; f += 320) {
        int ii = f >> 3, p = f & 7;
        int n = i0 + ii;
        float vx = srpg[ii][p * 3 + 0] - trans[n * 3 + 0];
        float vy = srpg[ii][p * 3 + 1] - trans[n * 3 + 1];
        float vz = srpg[ii][p * 3 + 2] - trans[n * 3 + 2];
        float nn = 1e-8f;
#pragma unroll
        for (int ic = 0; ic < 3; ic++) {
            float rl = rot[n * 9 + 0 + ic] * vx + rot[n * 9 + 3 + ic] * vy + rot[n * 9 + 6 + ic] * vz;
            g_final[(size_t)n * FINALD + 192 + ic * 96 + h * 8 + p] = rl;
            nn += rl * rl;
        }
        g_final[(size_t)n * FINALD + 480 + h * 8 + p] = sqrtf(nn);
    }
}

// ---------------- K5: output GEMM 768x384, K=2112, split-K=3 (f32x2) --------
__global__ __launch_bounds__(256) void k5_out(const float* __restrict__ out_w) {
    __shared__ float sA[32][65];
    __shared__ ull sB2[32][32];
    int tid = threadIdx.x, tx = tid & 15, ty = tid >> 4;
    int m0 = blockIdx.y * 64, n0 = blockIdx.x * 64;
    int kb = blockIdx.z * 704;
    ull acc[4][2] = {};
    for (int k0 = kb; k0 < kb + 704; k0 += 32) {
        for (int idx = tid; idx < 64 * 32; idx += 256) {
            int m = idx >> 5, kk = idx & 31;
            sA[kk][m] = g_final[(size_t)(m0 + m) * FINALD + k0 + kk];
        }
        for (int idx = tid; idx < 32 * 32; idx += 256) {
            int kk = idx >> 5, op = idx & 31;
            float2 wv = *(const float2*)(out_w + (size_t)(k0 + kk) * OUTD + n0 + op * 2);
            sB2[kk][op] = pk2two(wv.x, wv.y);
        }
        __syncthreads();
#pragma unroll
        for (int kk = 0; kk < 32; kk++) {
            ulonglong2 b01 = *(const ulonglong2*)&sB2[kk][tx * 2];
#pragma unroll
            for (int r = 0; r < 4; r++) {
                ull a2 = pk2(sA[kk][ty * 4 + r]);
                fma2(acc[r][0], a2, b01.x);
                fma2(acc[r][1], a2, b01.y);
            }
        }
        __syncthreads();
    }
#pragma unroll
    for (int r = 0; r < 4; r++) {
        int m = m0 + ty * 4 + r, o = n0 + tx * 4;
        float2 lo = upk(acc[r][0]), hi = upk(acc[r][1]);
        *(float4*)(g_part[blockIdx.z] + (size_t)m * OUTD + o) =
            make_float4(lo.x, lo.y, hi.x, hi.y);
    }
}

__global__ void k5r_reduce(const float* __restrict__ out_b, float* __restrict__ out) {
    int idx = blockIdx.x * 256 + threadIdx.x;
    if (idx < NRES * OUTD) {
        out[idx] = g_part[0][idx] + g_part[1][idx] + g_part[2][idx] + out_b[idx % OUTD];
    }
}

// ---------------- launch ----------------------------------------------------
extern "C" void kernel_launch(void* const* d_in, const int* in_sizes, int n_in,
                              void* d_out, int out_size) {
    const float* in1d  = (const float*)d_in[0];
    const float* in2d  = (const float*)d_in[1];
    const float* rot   = (const float*)d_in[2];
    const float* trans = (const float*)d_in[3];
    const float* qw    = (const float*)d_in[4];
    const float* qb    = (const float*)d_in[5];
    const float* kvw   = (const float*)d_in[6];
    const float* kvb   = (const float*)d_in[7];
    const float* qpw   = (const float*)d_in[8];
    const float* qpb   = (const float*)d_in[9];
    const float* kvpw  = (const float*)d_in[10];
    const float* kvpb  = (const float*)d_in[11];
    const float* tpw   = (const float*)d_in[12];
    const float* w2d   = (const float*)d_in[13];
    const float* b2d   = (const float*)d_in[14];
    const float* ow    = (const float*)d_in[15];
    const float* ob    = (const float*)d_in[16];
    float* out = (float*)d_out;

    cudaFuncSetAttribute(kfu, cudaFuncAttributeMaxDynamicSharedMemorySize, KFU_SMEM);

    k1a_gemm<<<dim3(18, 12), 256>>>(in1d, qw, qb, kvw, kvb, qpw, qpb, kvpw, kvpb);
    k1b_pack<<<768, 256>>>(rot, trans, tpw);
    k3_qk<<<dim3(96, 12), 256>>>();
    kfu<<<1536, 256, KFU_SMEM>>>(in2d, w2d, b2d);
    k4r_reduce<<<768, 256>>>();
    k3n_norm<<<dim3(96, 12), 256>>>();
    k4b_vattend<<<dim3(12, 12), 320>>>(rot, trans);
    k5_out<<<dim3(6, 12, 3), 256>>>(ow);
    k5r_reduce<<<1152, 256>>>(ob, out);
}

// round 16
// speedup vs baseline: 1.5790x; 1.5790x over previous
#include <cuda_runtime.h>
#include <math.h>

#define NRES 768
#define MSAD 384
#define NH 12
#define PAIRD 128
#define OUTD 384
#define PROJ 1152
#define FINALD 2112

typedef unsigned long long ull;

// ---------------- f32x2 helpers (Blackwell packed fp32) ---------------------
__device__ __forceinline__ ull pk2(float v) {
    ull r; asm("mov.b64 %0, {%1, %1};" : "=l"(r) : "f"(v)); return r;
}
__device__ __forceinline__ ull pk2two(float lo, float hi) {
    ull r; asm("mov.b64 %0, {%1, %2};" : "=l"(r) : "f"(lo), "f"(hi)); return r;
}
__device__ __forceinline__ void fma2(ull& d, ull a, ull b) {
    asm("fma.rn.f32x2 %0, %1, %2, %0;" : "+l"(d) : "l"(a), "l"(b));
}
__device__ __forceinline__ void add2(ull& d, ull b) {
    asm("add.rn.f32x2 %0, %0, %1;" : "+l"(d) : "l"(b));
}
__device__ __forceinline__ float2 upk(ull v) {
    float2 r; asm("mov.b64 {%0, %1}, %2;" : "=f"(r.x), "=f"(r.y) : "l"(v)); return r;
}
// ---------------- cp.async helpers ------------------------------------------
__device__ __forceinline__ void cp16(void* dst, const void* src) {
    unsigned d = (unsigned)__cvta_generic_to_shared(dst);
    asm volatile("cp.async.cg.shared.global [%0], [%1], 16;" :: "r"(d), "l"(src));
}
__device__ __forceinline__ void cp_commit() {
    asm volatile("cp.async.commit_group;" ::: "memory");
}
__device__ __forceinline__ void cp_wait2() {
    asm volatile("cp.async.wait_group 2;" ::: "memory");
}

// ---------------- scratch (device globals; no allocation allowed) ----------
__device__ float g_proj[NRES * PROJ];
__device__ float g_qpack[NH * NRES * 28];
__device__ float g_kpackT[NH * 32 * NRES];  // [h][d][j], d-major (d28 = bias)
__device__ float g_vpack2[NH * NRES * 40];
__device__ float g_logits[NH * NRES * NRES]; // a2d (k2) -> attn (k3)
__device__ float g_final[NRES * FINALD];
__device__ float g_part[6][NRES * OUTD];
__device__ float g_aovp[2][NRES * 1536];     // j-half partials of a_over_2d

// ---------------- K1a: projection GEMM 768x1152x384 (f32x2) -----------------
__global__ __launch_bounds__(256) void k1a_gemm(const float* __restrict__ in1d,
                                                const float* __restrict__ qw,  const float* __restrict__ qb,
                                                const float* __restrict__ kvw, const float* __restrict__ kvb,
                                                const float* __restrict__ qpw, const float* __restrict__ qpb,
                                                const float* __restrict__ kvpw,const float* __restrict__ kvpb) {
    __shared__ float sA[32][65];
    __shared__ ull sB2[32][32];
    int tid = threadIdx.x;
    int tx = tid & 15, ty = tid >> 4;
    int m0 = blockIdx.y * 64, n0 = blockIdx.x * 64;
    ull acc[4][2] = {};
    for (int k0 = 0; k0 < MSAD; k0 += 32) {
        for (int idx = tid; idx < 64 * 32; idx += 256) {
            int m = idx >> 5, kk = idx & 31;
            sA[kk][m] = in1d[(m0 + m) * MSAD + k0 + kk];
        }
        for (int idx = tid; idx < 32 * 32; idx += 256) {
            int kk = idx >> 5, op = idx & 31;
            int o = n0 + op * 2, k = k0 + kk;
            float2 w;
            if (o < 192)      w = *(const float2*)(qw + k * 192 + o);
            else if (o < 576) w = *(const float2*)(kvw + k * 384 + (o - 192));
            else if (o < 720) w = *(const float2*)(qpw + k * 144 + (o - 576));
            else              w = *(const float2*)(kvpw + k * 432 + (o - 720));
            sB2[kk][op] = pk2two(w.x, w.y);
        }
        __syncthreads();
#pragma unroll
        for (int kk = 0; kk < 32; kk++) {
            ulonglong2 b01 = *(const ulonglong2*)&sB2[kk][tx * 2];
#pragma unroll
            for (int r = 0; r < 4; r++) {
                ull a2 = pk2(sA[kk][ty * 4 + r]);
                fma2(acc[r][0], a2, b01.x);
                fma2(acc[r][1], a2, b01.y);
            }
        }
        __syncthreads();
    }
#pragma unroll
    for (int r = 0; r < 4; r++) {
        int m = m0 + ty * 4 + r, o = n0 + tx * 4;
        float2 lo = upk(acc[r][0]), hi = upk(acc[r][1]);
        float vv[4] = { lo.x, lo.y, hi.x, hi.y };
#pragma unroll
        for (int q = 0; q < 4; q++) {
            int oo = o + q;
            float b;
            if (oo < 192)      b = qb[oo];
            else if (oo < 576) b = kvb[oo - 192];
            else if (oo < 720) b = qpb[oo - 576];
            else               b = kvpb[oo - 720];
            g_proj[(size_t)m * PROJ + oo] = vv[q] + b;
        }
    }
}

// ---------------- K1b: apply rotations, pack q/k/v --------------------------
__global__ __launch_bounds__(256) void k1b_pack(const float* __restrict__ rot,
                                                const float* __restrict__ trans,
                                                const float* __restrict__ tpw) {
    __shared__ float sp[PROJ];
    __shared__ float srot[9], strans[3], spw[12];
    __shared__ float sg[192 * 3];
    int n = blockIdx.x, tid = threadIdx.x;
    for (int t = tid; t < PROJ; t += 256) sp[t] = g_proj[n * PROJ + t];
    if (tid < 9) srot[tid] = rot[n * 9 + tid];
    if (tid < 3) strans[tid] = trans[n * 3 + tid];
    if (tid < 12) {
        float x = tpw[tid];
        float sf = (x > 20.f) ? x : log1pf(__expf(x));
        spw[tid] = sf * 0.13608276348795434f; // sqrt(1/54)
    }
    __syncthreads();

    if (tid < 192) {
        int h = tid >> 4, d = tid & 15;
        g_qpack[(h * NRES + n) * 28 + d] = sp[tid] * 0.14433756729740643f; // 1/sqrt(48)
    }
    for (int t = tid; t < 384; t += 256) {
        int h = t >> 5, d = t & 31;
        if (d < 16) g_kpackT[((size_t)h * 32 + d) * NRES + n] = sp[192 + t];
        else        g_vpack2[((size_t)h * NRES + n) * 40 + (d - 16)] = sp[192 + t];
    }
    if (tid < 192) {
        float l0, l1, l2;
        if (tid < 48) { l0 = sp[576 + tid]; l1 = sp[576 + 48 + tid]; l2 = sp[576 + 96 + tid]; }
        else { int vs = tid - 48; l0 = sp[720 + vs]; l1 = sp[720 + 144 + vs]; l2 = sp[720 + 288 + vs]; }
#pragma unroll
        for (int c = 0; c < 3; c++)
            sg[tid * 3 + c] = srot[c * 3 + 0] * l0 + srot[c * 3 + 1] * l1 + srot[c * 3 + 2] * l2 + strans[c];
    }
    __syncthreads();
    if (tid < 48) {
        int h = tid >> 2, p = tid & 3;
        float pw = spw[h];
#pragma unroll
        for (int c = 0; c < 3; c++)
            g_qpack[(h * NRES + n) * 28 + 16 + p * 3 + c] = pw * sg[tid * 3 + c];
    } else if (tid < 192) {
        int vs = tid - 48, h = vs / 12, s = vs % 12;
        if (s < 4) {
#pragma unroll
            for (int c = 0; c < 3; c++)
                g_kpackT[((size_t)h * 32 + 16 + s * 3 + c) * NRES + n] = sg[tid * 3 + c];
        } else {
#pragma unroll
            for (int c = 0; c < 3; c++)
                g_vpack2[((size_t)h * NRES + n) * 40 + 16 + (s - 4) * 3 + c] = sg[tid * 3 + c];
        }
    }
    if (tid >= 192 && tid < 204) {
        int h = tid - 192;
        float s2 = 0.f;
        for (int s = 0; s < 4; s++)
            for (int c = 0; c < 3; c++) {
                float v = sg[(48 + h * 12 + s) * 3 + c];
                s2 += v * v;
            }
        g_kpackT[((size_t)h * 32 + 28) * NRES + n] = -0.5f * spw[h] * s2;
    }
}

// ---------------- K2: a2d GEMM, cp.async 3-buffer, 128-thr (6 blk/SM) -------
#define K2_SMEM 36928
__global__ __launch_bounds__(128) void k2_a2d(const float* __restrict__ in2d,
                                              const float* __restrict__ w2d,
                                              const float* __restrict__ b2d) {
    extern __shared__ char smraw[];
    float* sbuf = (float*)smraw;
    ull*   sw2  = (ull*)(smraw + 30720);
    float* sb   = (float*)(smraw + 36864);
    int tid = threadIdx.x;
    size_t p0 = (size_t)blockIdx.x * 128;
    const float* src = in2d + p0 * PAIRD;

#pragma unroll
    for (int s = 0; s < 2; s++) {
#pragma unroll
        for (int t = 0; t < 4; t++) {
            int f = tid + t * 128;
            int r = f >> 2, c4 = f & 3;
            cp16(sbuf + s * 2560 + r * 20 + c4 * 4,
                 src + (size_t)r * PAIRD + s * 16 + c4 * 4);
        }
        cp_commit();
    }
    for (int f = tid; f < 128 * 6; f += 128) {
        int c = f / 6, hp = f % 6;
        float2 w = *(const float2*)(w2d + c * 12 + hp * 2);
        sw2[f] = pk2two(w.x, w.y);
    }
    if (tid < 12) sb[tid] = b2d[tid];

    ull acc[6] = {};
#pragma unroll
    for (int ck = 0; ck < 8; ck++) {
        if (ck + 2 < 8) {
            int sn = ck + 2;
#pragma unroll
            for (int t = 0; t < 4; t++) {
                int f = tid + t * 128;
                int r = f >> 2, c4 = f & 3;
                cp16(sbuf + (sn % 3) * 2560 + r * 20 + c4 * 4,
                     src + (size_t)r * PAIRD + sn * 16 + c4 * 4);
            }
        }
        cp_commit();
        cp_wait2();
        __syncthreads();
        const float4* A4 = (const float4*)&sbuf[(ck % 3) * 2560 + tid * 20];
#pragma unroll
        for (int k4 = 0; k4 < 4; k4++) {
            float4 a = A4[k4];
#pragma unroll
            for (int q = 0; q < 4; q++) {
                float av = (q == 0) ? a.x : (q == 1) ? a.y : (q == 2) ? a.z : a.w;
                ull a2 = pk2(av);
                const ull* w = &sw2[(ck * 16 + k4 * 4 + q) * 6];
                ulonglong2 w01 = *(const ulonglong2*)(w + 0);
                ulonglong2 w23 = *(const ulonglong2*)(w + 2);
                ulonglong2 w45 = *(const ulonglong2*)(w + 4);
                fma2(acc[0], a2, w01.x); fma2(acc[1], a2, w01.y);
                fma2(acc[2], a2, w23.x); fma2(acc[3], a2, w23.y);
                fma2(acc[4], a2, w45.x); fma2(acc[5], a2, w45.y);
            }
        }
        __syncthreads();
    }
    size_t p = p0 + tid;
    int i = (int)(p / NRES), j = (int)(p % NRES);
    float res[12];
#pragma unroll
    for (int hp = 0; hp < 6; hp++) {
        float2 v = upk(acc[hp]);
        res[2 * hp] = v.x; res[2 * hp + 1] = v.y;
    }
#pragma unroll
    for (int h = 0; h < 12; h++)
        g_logits[((size_t)h * NRES + i) * NRES + j] = (res[h] + sb[h]) * 0.5773502691896258f;
}

// ---------------- K3: qk logits (coalesced kpackT) + softmax ----------------
__global__ __launch_bounds__(256) void k3_softmax() {
    __shared__ float srow[8][NRES];
    __shared__ ull su2[8][14];
    int h = blockIdx.y, i0 = blockIdx.x * 8;
    int tid = threadIdx.x;
    for (int t = tid; t < 8 * 14; t += 256) {
        int i8 = t / 14, dp = t % 14;
        const float* qp = g_qpack + ((size_t)h * NRES + (i0 + i8)) * 28 + dp * 2;
        su2[i8][dp] = pk2two(qp[0], qp[1]);
    }
    __syncthreads();
    const float* kbase = g_kpackT + (size_t)h * 32 * NRES;
    for (int jj = 0; jj < 3; jj++) {
        int j = jj * 256 + tid;
        const float* kb = kbase + j;
        ull wr2[14];
#pragma unroll
        for (int dp = 0; dp < 14; dp++)
            wr2[dp] = pk2two(__ldg(kb + (size_t)(2 * dp) * NRES),
                             __ldg(kb + (size_t)(2 * dp + 1) * NRES));
        float bias = __ldg(kb + (size_t)28 * NRES);
#pragma unroll
        for (int i8 = 0; i8 < 8; i8++) {
            ull acc2 = 0;
#pragma unroll
            for (int dp = 0; dp < 14; dp++) fma2(acc2, su2[i8][dp], wr2[dp]);
            float2 t = upk(acc2);
            srow[i8][j] = t.x + t.y + bias
                        + g_logits[((size_t)h * NRES + (i0 + i8)) * NRES + j];
        }
    }
    __syncthreads();
    int w = tid >> 5, lane = tid & 31;
    float vals[24];
    float m = -1e30f;
#pragma unroll
    for (int t = 0; t < 24; t++) {
        vals[t] = srow[w][t * 32 + lane];
        m = fmaxf(m, vals[t]);
    }
#pragma unroll
    for (int o = 16; o > 0; o >>= 1) m = fmaxf(m, __shfl_xor_sync(~0u, m, o));
    float s = 0.f;
#pragma unroll
    for (int t = 0; t < 24; t++) {
        float e = __expf(vals[t] - m);
        vals[t] = e; s += e;
    }
#pragma unroll
    for (int o = 16; o > 0; o >>= 1) s += __shfl_xor_sync(~0u, s, o);
    float inv = 1.f / s;
    float* dst = g_logits + ((size_t)h * NRES + (i0 + w)) * NRES;
#pragma unroll
    for (int t = 0; t < 24; t++) dst[t * 32 + lane] = vals[t] * inv;
}

// ---------------- K4a: a_over_2d, j-split (block = (i, jh)) -----------------
// smem: sattnT float[384*12] @0 (18432), sbuf float[4][16*128] @18432 (32768)
#define K4A_SMEM 51200
__global__ __launch_bounds__(256) void k4a_aover(const float* __restrict__ in2d) {
    extern __shared__ char smraw[];
    float* sattnT = (float*)smraw;            // [jl][12]
    float* sbuf   = (float*)(smraw + 18432);
    int i = blockIdx.x >> 1, jh = blockIdx.x & 1;
    int tid = threadIdx.x;

    const float* src = in2d + ((size_t)i * NRES + jh * 384) * PAIRD;
#pragma unroll
    for (int s = 0; s < 3; s++) {
#pragma unroll
        for (int t = 0; t < 2; t++) {
            int f = tid + t * 256;
            int r = f >> 5, c4 = f & 31;
            cp16(sbuf + s * 2048 + r * 128 + c4 * 4,
                 src + (size_t)(s * 16 + r) * PAIRD + c4 * 4);
        }
        cp_commit();
    }
    for (int f = tid; f < 4608; f += 256) {
        int h = f / 384, jl = f % 384;
        sattnT[jl * 12 + h] =
            __ldg(g_logits + ((size_t)h * NRES + i) * NRES + jh * 384 + jl);
    }
    __syncthreads();

    int rg = tid >> 6, cp = tid & 63;
    ull acc[12] = {};

    for (int s = 0; s < 24; s++) {
        cp_wait2();
        __syncthreads();
        if (s + 3 < 24) {
            int sn = s + 3;
#pragma unroll
            for (int t = 0; t < 2; t++) {
                int f = tid + t * 256;
                int r = f >> 5, c4 = f & 31;
                cp16(sbuf + (sn & 3) * 2048 + r * 128 + c4 * 4,
                     src + (size_t)(sn * 16 + r) * PAIRD + c4 * 4);
            }
        }
        cp_commit();
        const ull* bb = (const ull*)(sbuf + (s & 3) * 2048);
        int j0 = s * 16;
#pragma unroll
        for (int r = 0; r < 4; r++) {
            int jl = rg * 4 + r;
            ull d = bb[jl * 64 + cp];
            const float4* ap = (const float4*)&sattnT[(j0 + jl) * 12];
            float4 a0 = ap[0], a1 = ap[1], a2v = ap[2];
            fma2(acc[0], pk2(a0.x), d);  fma2(acc[1], pk2(a0.y), d);
            fma2(acc[2], pk2(a0.z), d);  fma2(acc[3], pk2(a0.w), d);
            fma2(acc[4], pk2(a1.x), d);  fma2(acc[5], pk2(a1.y), d);
            fma2(acc[6], pk2(a1.z), d);  fma2(acc[7], pk2(a1.w), d);
            fma2(acc[8], pk2(a2v.x), d); fma2(acc[9], pk2(a2v.y), d);
            fma2(acc[10], pk2(a2v.z), d); fma2(acc[11], pk2(a2v.w), d);
        }
    }
    __syncthreads();
    ull* red = (ull*)sbuf;   // [256][13] ull = 26624 B <= 32768
#pragma unroll
    for (int h = 0; h < 12; h++) red[(rg * 64 + cp) * 13 + h] = acc[h];
    __syncthreads();
    float* dstp = g_aovp[jh] + (size_t)i * 1536;
    for (int pi = tid; pi < 768; pi += 256) {
        int h = pi >> 6, c2 = pi & 63;
        ull t0 = red[(0 * 64 + c2) * 13 + h];
        add2(t0, red[(1 * 64 + c2) * 13 + h]);
        add2(t0, red[(2 * 64 + c2) * 13 + h]);
        add2(t0, red[(3 * 64 + c2) * 13 + h]);
        float2 v = upk(t0);
        *(float2*)(dstp + h * PAIRD + 2 * c2) = v;
    }
}

// ---------------- K4r: combine j-half partials into g_final -----------------
__global__ void k4r_reduce() {
    int idx = blockIdx.x * 256 + threadIdx.x;
    if (idx < NRES * 1536) {
        int i = idx / 1536, x = idx % 1536;
        g_final[(size_t)i * FINALD + 576 + x] = g_aovp[0][idx] + g_aovp[1][idx];
    }
}

// ---------------- K4b: per-head GEMM for v / vp (i-tile 32, 288 blocks) -----
__global__ __launch_bounds__(320) void k4b_vattend(const float* __restrict__ rot,
                                                   const float* __restrict__ trans) {
    __shared__ float2 sattn2[32][65];
    __shared__ ull svp[64 * 20];
    __shared__ float srpg[32][24];
    int i0 = blockIdx.x * 32, h = blockIdx.y;
    int tid = threadIdx.x, il = tid & 31, dg = tid >> 5;  // dg: 0..9, 4 dims each
    ull acc[2] = {};
    for (int j0 = 0; j0 < NRES; j0 += 64) {
        for (int f = tid; f < 2048; f += 320) {
            int r = f >> 6, c = f & 63;
            float a = g_logits[((size_t)h * NRES + i0 + r) * NRES + j0 + c];
            sattn2[r][c] = make_float2(a, a);
        }
        for (int f = tid; f < 1280; f += 320)
            svp[f] = __ldg((const ull*)(g_vpack2 + ((size_t)h * NRES + j0) * 40) + f);
        __syncthreads();
#pragma unroll 4
        for (int jj = 0; jj < 64; jj++) {
            ull a2 = *(const ull*)&sattn2[il][jj];
            ulonglong2 wv = *(const ulonglong2*)&svp[jj * 20 + dg * 2];
            fma2(acc[0], a2, wv.x); fma2(acc[1], a2, wv.y);
        }
        __syncthreads();
    }
    int n_i = i0 + il;
    float v[4];
    {
        float2 t0 = upk(acc[0]), t1 = upk(acc[1]);
        v[0] = t0.x; v[1] = t0.y; v[2] = t1.x; v[3] = t1.y;
    }
    if (dg < 4) {
        float* dst = g_final + (size_t)n_i * FINALD + h * 16 + dg * 4;
#pragma unroll
        for (int t = 0; t < 4; t++) dst[t] = v[t];
    } else {
        int d0 = (dg - 4) * 4;
#pragma unroll
        for (int t = 0; t < 4; t++) srpg[il][d0 + t] = v[t];
    }
    __syncthreads();
    if (tid < 256) {
        int ii = tid >> 3, p = tid & 7;
        int n = i0 + ii;
        float vx = srpg[ii][p * 3 + 0] - trans[n * 3 + 0];
        float vy = srpg[ii][p * 3 + 1] - trans[n * 3 + 1];
        float vz = srpg[ii][p * 3 + 2] - trans[n * 3 + 2];
        float nn = 1e-8f;
#pragma unroll
        for (int ic = 0; ic < 3; ic++) {
            float rl = rot[n * 9 + 0 + ic] * vx + rot[n * 9 + 3 + ic] * vy + rot[n * 9 + 6 + ic] * vz;
            g_final[(size_t)n * FINALD + 192 + ic * 96 + h * 8 + p] = rl;
            nn += rl * rl;
        }
        g_final[(size_t)n * FINALD + 480 + h * 8 + p] = sqrtf(nn);
    }
}

// ---------------- K5: output GEMM 768x384, K=2112, split-K=6 (f32x2) --------
__global__ __launch_bounds__(256) void k5_out(const float* __restrict__ out_w) {
    __shared__ float sA[32][65];
    __shared__ ull sB2[32][32];
    int tid = threadIdx.x, tx = tid & 15, ty = tid >> 4;
    int m0 = blockIdx.y * 64, n0 = blockIdx.x * 64;
    int kb = blockIdx.z * 352;
    ull acc[4][2] = {};
    for (int k0 = kb; k0 < kb + 352; k0 += 32) {
        for (int idx = tid; idx < 64 * 32; idx += 256) {
            int m = idx >> 5, kk = idx & 31;
            sA[kk][m] = g_final[(size_t)(m0 + m) * FINALD + k0 + kk];
        }
        for (int idx = tid; idx < 32 * 32; idx += 256) {
            int kk = idx >> 5, op = idx & 31;
            float2 wv = *(const float2*)(out_w + (size_t)(k0 + kk) * OUTD + n0 + op * 2);
            sB2[kk][op] = pk2two(wv.x, wv.y);
        }
        __syncthreads();
#pragma unroll
        for (int kk = 0; kk < 32; kk++) {
            ulonglong2 b01 = *(const ulonglong2*)&sB2[kk][tx * 2];
#pragma unroll
            for (int r = 0; r < 4; r++) {
                ull a2 = pk2(sA[kk][ty * 4 + r]);
                fma2(acc[r][0], a2, b01.x);
                fma2(acc[r][1], a2, b01.y);
            }
        }
        __syncthreads();
    }
#pragma unroll
    for (int r = 0; r < 4; r++) {
        int m = m0 + ty * 4 + r, o = n0 + tx * 4;
        float2 lo = upk(acc[r][0]), hi = upk(acc[r][1]);
        *(float4*)(g_part[blockIdx.z] + (size_t)m * OUTD + o) =
            make_float4(lo.x, lo.y, hi.x, hi.y);
    }
}

__global__ void k5r_reduce(const float* __restrict__ out_b, float* __restrict__ out) {
    int idx = blockIdx.x * 256 + threadIdx.x;
    if (idx < NRES * OUTD) {
        out[idx] = g_part[0][idx] + g_part[1][idx] + g_part[2][idx]
                 + g_part[3][idx] + g_part[4][idx] + g_part[5][idx] + out_b[idx % OUTD];
    }
}

// ---------------- launch ----------------------------------------------------
extern "C" void kernel_launch(void* const* d_in, const int* in_sizes, int n_in,
                              void* d_out, int out_size) {
    const float* in1d  = (const float*)d_in[0];
    const float* in2d  = (const float*)d_in[1];
    const float* rot   = (const float*)d_in[2];
    const float* trans = (const float*)d_in[3];
    const float* qw    = (const float*)d_in[4];
    const float* qb    = (const float*)d_in[5];
    const float* kvw   = (const float*)d_in[6];
    const float* kvb   = (const float*)d_in[7];
    const float* qpw   = (const float*)d_in[8];
    const float* qpb   = (const float*)d_in[9];
    const float* kvpw  = (const float*)d_in[10];
    const float* kvpb  = (const float*)d_in[11];
    const float* tpw   = (const float*)d_in[12];
    const float* w2d   = (const float*)d_in[13];
    const float* b2d   = (const float*)d_in[14];
    const float* ow    = (const float*)d_in[15];
    const float* ob    = (const float*)d_in[16];
    float* out = (float*)d_out;

    cudaFuncSetAttribute(k2_a2d, cudaFuncAttributeMaxDynamicSharedMemorySize, K2_SMEM);
    cudaFuncSetAttribute(k4a_aover, cudaFuncAttributeMaxDynamicSharedMemorySize, K4A_SMEM);

    k1a_gemm<<<dim3(18, 12), 256>>>(in1d, qw, qb, kvw, kvb, qpw, qpb, kvpw, kvpb);
    k1b_pack<<<768, 256>>>(rot, trans, tpw);
    k2_a2d<<<4608, 128, K2_SMEM>>>(in2d, w2d, b2d);
    k3_softmax<<<dim3(96, 12), 256>>>();
    k4a_aover<<<1536, 256, K4A_SMEM>>>(in2d);
    k4r_reduce<<<4608, 256>>>();
    k4b_vattend<<<dim3(24, 12), 320>>>(rot, trans);
    k5_out<<<dim3(6, 12, 6), 256>>>(ow);
    k5r_reduce<<<1152, 256>>>(ob, out);
}

// round 17
// speedup vs baseline: 1.6517x; 1.0460x over previous
#include <cuda_runtime.h>
#include <math.h>

#define NRES 768
#define MSAD 384
#define NH 12
#define PAIRD 128
#define OUTD 384
#define PROJ 1152
#define FINALD 2112

typedef unsigned long long ull;

// ---------------- f32x2 helpers (Blackwell packed fp32) ---------------------
__device__ __forceinline__ ull pk2(float v) {
    ull r; asm("mov.b64 %0, {%1, %1};" : "=l"(r) : "f"(v)); return r;
}
__device__ __forceinline__ ull pk2two(float lo, float hi) {
    ull r; asm("mov.b64 %0, {%1, %2};" : "=l"(r) : "f"(lo), "f"(hi)); return r;
}
__device__ __forceinline__ void fma2(ull& d, ull a, ull b) {
    asm("fma.rn.f32x2 %0, %1, %2, %0;" : "+l"(d) : "l"(a), "l"(b));
}
__device__ __forceinline__ void add2(ull& d, ull b) {
    asm("add.rn.f32x2 %0, %0, %1;" : "+l"(d) : "l"(b));
}
__device__ __forceinline__ float2 upk(ull v) {
    float2 r; asm("mov.b64 {%0, %1}, %2;" : "=f"(r.x), "=f"(r.y) : "l"(v)); return r;
}
// ---------------- cp.async helpers ------------------------------------------
__device__ __forceinline__ void cp16(void* dst, const void* src) {
    unsigned d = (unsigned)__cvta_generic_to_shared(dst);
    asm volatile("cp.async.cg.shared.global [%0], [%1], 16;" :: "r"(d), "l"(src));
}
__device__ __forceinline__ void cp_commit() {
    asm volatile("cp.async.commit_group;" ::: "memory");
}
__device__ __forceinline__ void cp_wait2() {
    asm volatile("cp.async.wait_group 2;" ::: "memory");
}

// ---------------- scratch (device globals; no allocation allowed) ----------
__device__ float g_proj[NRES * PROJ];
__device__ float g_qpack[NH * NRES * 28];
__device__ float g_kpackT[NH * 32 * NRES];  // [h][d][j], d-major (d28 = bias)
__device__ float g_vpack2[NH * NRES * 40];
__device__ float g_logits[NH * NRES * NRES]; // a2d (k2) -> attn (k3)
__device__ float g_final[NRES * FINALD];
__device__ float g_part[6][NRES * OUTD];
__device__ float g_aovp[2][NRES * 1536];     // j-half partials of a_over_2d

// ---------------- K1a: projection GEMM 768x1152x384 (f32x2) -----------------
__global__ __launch_bounds__(256) void k1a_gemm(const float* __restrict__ in1d,
                                                const float* __restrict__ qw,  const float* __restrict__ qb,
                                                const float* __restrict__ kvw, const float* __restrict__ kvb,
                                                const float* __restrict__ qpw, const float* __restrict__ qpb,
                                                const float* __restrict__ kvpw,const float* __restrict__ kvpb) {
    __shared__ float sA[32][65];
    __shared__ ull sB2[32][32];
    int tid = threadIdx.x;
    int tx = tid & 15, ty = tid >> 4;
    int m0 = blockIdx.y * 64, n0 = blockIdx.x * 64;
    ull acc[4][2] = {};
    for (int k0 = 0; k0 < MSAD; k0 += 32) {
        for (int idx = tid; idx < 64 * 32; idx += 256) {
            int m = idx >> 5, kk = idx & 31;
            sA[kk][m] = in1d[(m0 + m) * MSAD + k0 + kk];
        }
        for (int idx = tid; idx < 32 * 32; idx += 256) {
            int kk = idx >> 5, op = idx & 31;
            int o = n0 + op * 2, k = k0 + kk;
            float2 w;
            if (o < 192)      w = *(const float2*)(qw + k * 192 + o);
            else if (o < 576) w = *(const float2*)(kvw + k * 384 + (o - 192));
            else if (o < 720) w = *(const float2*)(qpw + k * 144 + (o - 576));
            else              w = *(const float2*)(kvpw + k * 432 + (o - 720));
            sB2[kk][op] = pk2two(w.x, w.y);
        }
        __syncthreads();
#pragma unroll
        for (int kk = 0; kk < 32; kk++) {
            ulonglong2 b01 = *(const ulonglong2*)&sB2[kk][tx * 2];
#pragma unroll
            for (int r = 0; r < 4; r++) {
                ull a2 = pk2(sA[kk][ty * 4 + r]);
                fma2(acc[r][0], a2, b01.x);
                fma2(acc[r][1], a2, b01.y);
            }
        }
        __syncthreads();
    }
#pragma unroll
    for (int r = 0; r < 4; r++) {
        int m = m0 + ty * 4 + r, o = n0 + tx * 4;
        float2 lo = upk(acc[r][0]), hi = upk(acc[r][1]);
        float vv[4] = { lo.x, lo.y, hi.x, hi.y };
#pragma unroll
        for (int q = 0; q < 4; q++) {
            int oo = o + q;
            float b;
            if (oo < 192)      b = qb[oo];
            else if (oo < 576) b = kvb[oo - 192];
            else if (oo < 720) b = qpb[oo - 576];
            else               b = kvpb[oo - 720];
            g_proj[(size_t)m * PROJ + oo] = vv[q] + b;
        }
    }
}

// ---------------- K1b: apply rotations, pack q/k/v --------------------------
__global__ __launch_bounds__(256) void k1b_pack(const float* __restrict__ rot,
                                                const float* __restrict__ trans,
                                                const float* __restrict__ tpw) {
    __shared__ float sp[PROJ];
    __shared__ float srot[9], strans[3], spw[12];
    __shared__ float sg[192 * 3];
    int n = blockIdx.x, tid = threadIdx.x;
    for (int t = tid; t < PROJ; t += 256) sp[t] = g_proj[n * PROJ + t];
    if (tid < 9) srot[tid] = rot[n * 9 + tid];
    if (tid < 3) strans[tid] = trans[n * 3 + tid];
    if (tid < 12) {
        float x = tpw[tid];
        float sf = (x > 20.f) ? x : log1pf(__expf(x));
        spw[tid] = sf * 0.13608276348795434f; // sqrt(1/54)
    }
    __syncthreads();

    if (tid < 192) {
        int h = tid >> 4, d = tid & 15;
        g_qpack[(h * NRES + n) * 28 + d] = sp[tid] * 0.14433756729740643f; // 1/sqrt(48)
    }
    for (int t = tid; t < 384; t += 256) {
        int h = t >> 5, d = t & 31;
        if (d < 16) g_kpackT[((size_t)h * 32 + d) * NRES + n] = sp[192 + t];
        else        g_vpack2[((size_t)h * NRES + n) * 40 + (d - 16)] = sp[192 + t];
    }
    if (tid < 192) {
        float l0, l1, l2;
        if (tid < 48) { l0 = sp[576 + tid]; l1 = sp[576 + 48 + tid]; l2 = sp[576 + 96 + tid]; }
        else { int vs = tid - 48; l0 = sp[720 + vs]; l1 = sp[720 + 144 + vs]; l2 = sp[720 + 288 + vs]; }
#pragma unroll
        for (int c = 0; c < 3; c++)
            sg[tid * 3 + c] = srot[c * 3 + 0] * l0 + srot[c * 3 + 1] * l1 + srot[c * 3 + 2] * l2 + strans[c];
    }
    __syncthreads();
    if (tid < 48) {
        int h = tid >> 2, p = tid & 3;
        float pw = spw[h];
#pragma unroll
        for (int c = 0; c < 3; c++)
            g_qpack[(h * NRES + n) * 28 + 16 + p * 3 + c] = pw * sg[tid * 3 + c];
    } else if (tid < 192) {
        int vs = tid - 48, h = vs / 12, s = vs % 12;
        if (s < 4) {
#pragma unroll
            for (int c = 0; c < 3; c++)
                g_kpackT[((size_t)h * 32 + 16 + s * 3 + c) * NRES + n] = sg[tid * 3 + c];
        } else {
#pragma unroll
            for (int c = 0; c < 3; c++)
                g_vpack2[((size_t)h * NRES + n) * 40 + 16 + (s - 4) * 3 + c] = sg[tid * 3 + c];
        }
    }
    if (tid >= 192 && tid < 204) {
        int h = tid - 192;
        float s2 = 0.f;
        for (int s = 0; s < 4; s++)
            for (int c = 0; c < 3; c++) {
                float v = sg[(48 + h * 12 + s) * 3 + c];
                s2 += v * v;
            }
        g_kpackT[((size_t)h * 32 + 28) * NRES + n] = -0.5f * spw[h] * s2;
    }
}

// ---------------- K2: a2d GEMM, cp.async 3-buffer, 128-thr (6 blk/SM) -------
#define K2_SMEM 36928
__global__ __launch_bounds__(128) void k2_a2d(const float* __restrict__ in2d,
                                              const float* __restrict__ w2d,
                                              const float* __restrict__ b2d) {
    extern __shared__ char smraw[];
    float* sbuf = (float*)smraw;
    ull*   sw2  = (ull*)(smraw + 30720);
    float* sb   = (float*)(smraw + 36864);
    int tid = threadIdx.x;
    size_t p0 = (size_t)blockIdx.x * 128;
    const float* src = in2d + p0 * PAIRD;

#pragma unroll
    for (int s = 0; s < 2; s++) {
#pragma unroll
        for (int t = 0; t < 4; t++) {
            int f = tid + t * 128;
            int r = f >> 2, c4 = f & 3;
            cp16(sbuf + s * 2560 + r * 20 + c4 * 4,
                 src + (size_t)r * PAIRD + s * 16 + c4 * 4);
        }
        cp_commit();
    }
    for (int f = tid; f < 128 * 6; f += 128) {
        int c = f / 6, hp = f % 6;
        float2 w = *(const float2*)(w2d + c * 12 + hp * 2);
        sw2[f] = pk2two(w.x, w.y);
    }
    if (tid < 12) sb[tid] = b2d[tid];

    ull acc[6] = {};
#pragma unroll
    for (int ck = 0; ck < 8; ck++) {
        if (ck + 2 < 8) {
            int sn = ck + 2;
#pragma unroll
            for (int t = 0; t < 4; t++) {
                int f = tid + t * 128;
                int r = f >> 2, c4 = f & 3;
                cp16(sbuf + (sn % 3) * 2560 + r * 20 + c4 * 4,
                     src + (size_t)r * PAIRD + sn * 16 + c4 * 4);
            }
        }
        cp_commit();
        cp_wait2();
        __syncthreads();
        const float4* A4 = (const float4*)&sbuf[(ck % 3) * 2560 + tid * 20];
#pragma unroll
        for (int k4 = 0; k4 < 4; k4++) {
            float4 a = A4[k4];
#pragma unroll
            for (int q = 0; q < 4; q++) {
                float av = (q == 0) ? a.x : (q == 1) ? a.y : (q == 2) ? a.z : a.w;
                ull a2 = pk2(av);
                const ull* w = &sw2[(ck * 16 + k4 * 4 + q) * 6];
                ulonglong2 w01 = *(const ulonglong2*)(w + 0);
                ulonglong2 w23 = *(const ulonglong2*)(w + 2);
                ulonglong2 w45 = *(const ulonglong2*)(w + 4);
                fma2(acc[0], a2, w01.x); fma2(acc[1], a2, w01.y);
                fma2(acc[2], a2, w23.x); fma2(acc[3], a2, w23.y);
                fma2(acc[4], a2, w45.x); fma2(acc[5], a2, w45.y);
            }
        }
        __syncthreads();
    }
    size_t p = p0 + tid;
    int i = (int)(p / NRES), j = (int)(p % NRES);
    float res[12];
#pragma unroll
    for (int hp = 0; hp < 6; hp++) {
        float2 v = upk(acc[hp]);
        res[2 * hp] = v.x; res[2 * hp + 1] = v.y;
    }
#pragma unroll
    for (int h = 0; h < 12; h++)
        g_logits[((size_t)h * NRES + i) * NRES + j] = (res[h] + sb[h]) * 0.5773502691896258f;
}

// ---------------- K3: qk logits (coalesced kpackT) + softmax ----------------
__global__ __launch_bounds__(256) void k3_softmax() {
    __shared__ float srow[8][NRES];
    __shared__ ull su2[8][14];
    int h = blockIdx.y, i0 = blockIdx.x * 8;
    int tid = threadIdx.x;
    for (int t = tid; t < 8 * 14; t += 256) {
        int i8 = t / 14, dp = t % 14;
        const float* qp = g_qpack + ((size_t)h * NRES + (i0 + i8)) * 28 + dp * 2;
        su2[i8][dp] = pk2two(qp[0], qp[1]);
    }
    __syncthreads();
    const float* kbase = g_kpackT + (size_t)h * 32 * NRES;
    for (int jj = 0; jj < 3; jj++) {
        int j = jj * 256 + tid;
        const float* kb = kbase + j;
        ull wr2[14];
#pragma unroll
        for (int dp = 0; dp < 14; dp++)
            wr2[dp] = pk2two(__ldg(kb + (size_t)(2 * dp) * NRES),
                             __ldg(kb + (size_t)(2 * dp + 1) * NRES));
        float bias = __ldg(kb + (size_t)28 * NRES);
#pragma unroll
        for (int i8 = 0; i8 < 8; i8++) {
            ull acc2 = 0;
#pragma unroll
            for (int dp = 0; dp < 14; dp++) fma2(acc2, su2[i8][dp], wr2[dp]);
            float2 t = upk(acc2);
            srow[i8][j] = t.x + t.y + bias
                        + g_logits[((size_t)h * NRES + (i0 + i8)) * NRES + j];
        }
    }
    __syncthreads();
    int w = tid >> 5, lane = tid & 31;
    float vals[24];
    float m = -1e30f;
#pragma unroll
    for (int t = 0; t < 24; t++) {
        vals[t] = srow[w][t * 32 + lane];
        m = fmaxf(m, vals[t]);
    }
#pragma unroll
    for (int o = 16; o > 0; o >>= 1) m = fmaxf(m, __shfl_xor_sync(~0u, m, o));
    float s = 0.f;
#pragma unroll
    for (int t = 0; t < 24; t++) {
        float e = __expf(vals[t] - m);
        vals[t] = e; s += e;
    }
#pragma unroll
    for (int o = 16; o > 0; o >>= 1) s += __shfl_xor_sync(~0u, s, o);
    float inv = 1.f / s;
    float* dst = g_logits + ((size_t)h * NRES + (i0 + w)) * NRES;
#pragma unroll
    for (int t = 0; t < 24; t++) dst[t * 32 + lane] = vals[t] * inv;
}

// ---------------- K4a: a_over_2d, j-split (block = (i, jh)) -----------------
#define K4A_SMEM 51200
__global__ __launch_bounds__(256) void k4a_aover(const float* __restrict__ in2d) {
    extern __shared__ char smraw[];
    float* sattnT = (float*)smraw;            // [jl][12]
    float* sbuf   = (float*)(smraw + 18432);
    int i = blockIdx.x >> 1, jh = blockIdx.x & 1;
    int tid = threadIdx.x;

    const float* src = in2d + ((size_t)i * NRES + jh * 384) * PAIRD;
#pragma unroll
    for (int s = 0; s < 3; s++) {
#pragma unroll
        for (int t = 0; t < 2; t++) {
            int f = tid + t * 256;
            int r = f >> 5, c4 = f & 31;
            cp16(sbuf + s * 2048 + r * 128 + c4 * 4,
                 src + (size_t)(s * 16 + r) * PAIRD + c4 * 4);
        }
        cp_commit();
    }
    for (int f = tid; f < 4608; f += 256) {
        int h = f / 384, jl = f % 384;
        sattnT[jl * 12 + h] =
            __ldg(g_logits + ((size_t)h * NRES + i) * NRES + jh * 384 + jl);
    }
    __syncthreads();

    int rg = tid >> 6, cp = tid & 63;
    ull acc[12] = {};

    for (int s = 0; s < 24; s++) {
        cp_wait2();
        __syncthreads();
        if (s + 3 < 24) {
            int sn = s + 3;
#pragma unroll
            for (int t = 0; t < 2; t++) {
                int f = tid + t * 256;
                int r = f >> 5, c4 = f & 31;
                cp16(sbuf + (sn & 3) * 2048 + r * 128 + c4 * 4,
                     src + (size_t)(sn * 16 + r) * PAIRD + c4 * 4);
            }
        }
        cp_commit();
        const ull* bb = (const ull*)(sbuf + (s & 3) * 2048);
        int j0 = s * 16;
#pragma unroll
        for (int r = 0; r < 4; r++) {
            int jl = rg * 4 + r;
            ull d = bb[jl * 64 + cp];
            const float4* ap = (const float4*)&sattnT[(j0 + jl) * 12];
            float4 a0 = ap[0], a1 = ap[1], a2v = ap[2];
            fma2(acc[0], pk2(a0.x), d);  fma2(acc[1], pk2(a0.y), d);
            fma2(acc[2], pk2(a0.z), d);  fma2(acc[3], pk2(a0.w), d);
            fma2(acc[4], pk2(a1.x), d);  fma2(acc[5], pk2(a1.y), d);
            fma2(acc[6], pk2(a1.z), d);  fma2(acc[7], pk2(a1.w), d);
            fma2(acc[8], pk2(a2v.x), d); fma2(acc[9], pk2(a2v.y), d);
            fma2(acc[10], pk2(a2v.z), d); fma2(acc[11], pk2(a2v.w), d);
        }
    }
    __syncthreads();
    ull* red = (ull*)sbuf;   // [256][13] ull = 26624 B <= 32768
#pragma unroll
    for (int h = 0; h < 12; h++) red[(rg * 64 + cp) * 13 + h] = acc[h];
    __syncthreads();
    float* dstp = g_aovp[jh] + (size_t)i * 1536;
    for (int pi = tid; pi < 768; pi += 256) {
        int h = pi >> 6, c2 = pi & 63;
        ull t0 = red[(0 * 64 + c2) * 13 + h];
        add2(t0, red[(1 * 64 + c2) * 13 + h]);
        add2(t0, red[(2 * 64 + c2) * 13 + h]);
        add2(t0, red[(3 * 64 + c2) * 13 + h]);
        float2 v = upk(t0);
        *(float2*)(dstp + h * PAIRD + 2 * c2) = v;
    }
}

// ---------------- K4r: combine j-half partials into g_final -----------------
__global__ void k4r_reduce() {
    int idx = blockIdx.x * 256 + threadIdx.x;
    if (idx < NRES * 1536) {
        int i = idx / 1536, x = idx % 1536;
        g_final[(size_t)i * FINALD + 576 + x] = g_aovp[0][idx] + g_aovp[1][idx];
    }
}

// ---------------- K4b: per-head GEMM for v / vp (i-tile 32, 288 blocks) -----
__global__ __launch_bounds__(320) void k4b_vattend(const float* __restrict__ rot,
                                                   const float* __restrict__ trans) {
    __shared__ float2 sattn2[32][65];
    __shared__ ull svp[64 * 20];
    __shared__ float srpg[32][24];
    int i0 = blockIdx.x * 32, h = blockIdx.y;
    int tid = threadIdx.x, il = tid & 31, dg = tid >> 5;  // dg: 0..9, 4 dims each
    ull acc[2] = {};
    for (int j0 = 0; j0 < NRES; j0 += 64) {
        for (int f = tid; f < 2048; f += 320) {
            int r = f >> 6, c = f & 63;
            float a = g_logits[((size_t)h * NRES + i0 + r) * NRES + j0 + c];
            sattn2[r][c] = make_float2(a, a);
        }
        for (int f = tid; f < 1280; f += 320)
            svp[f] = __ldg((const ull*)(g_vpack2 + ((size_t)h * NRES + j0) * 40) + f);
        __syncthreads();
#pragma unroll 4
        for (int jj = 0; jj < 64; jj++) {
            ull a2 = *(const ull*)&sattn2[il][jj];
            ulonglong2 wv = *(const ulonglong2*)&svp[jj * 20 + dg * 2];
            fma2(acc[0], a2, wv.x); fma2(acc[1], a2, wv.y);
        }
        __syncthreads();
    }
    int n_i = i0 + il;
    float v[4];
    {
        float2 t0 = upk(acc[0]), t1 = upk(acc[1]);
        v[0] = t0.x; v[1] = t0.y; v[2] = t1.x; v[3] = t1.y;
    }
    if (dg < 4) {
        float* dst = g_final + (size_t)n_i * FINALD + h * 16 + dg * 4;
#pragma unroll
        for (int t = 0; t < 4; t++) dst[t] = v[t];
    } else {
        int d0 = (dg - 4) * 4;
#pragma unroll
        for (int t = 0; t < 4; t++) srpg[il][d0 + t] = v[t];
    }
    __syncthreads();
    if (tid < 256) {
        int ii = tid >> 3, p = tid & 7;
        int n = i0 + ii;
        float vx = srpg[ii][p * 3 + 0] - trans[n * 3 + 0];
        float vy = srpg[ii][p * 3 + 1] - trans[n * 3 + 1];
        float vz = srpg[ii][p * 3 + 2] - trans[n * 3 + 2];
        float nn = 1e-8f;
#pragma unroll
        for (int ic = 0; ic < 3; ic++) {
            float rl = rot[n * 9 + 0 + ic] * vx + rot[n * 9 + 3 + ic] * vy + rot[n * 9 + 6 + ic] * vz;
            g_final[(size_t)n * FINALD + 192 + ic * 96 + h * 8 + p] = rl;
            nn += rl * rl;
        }
        g_final[(size_t)n * FINALD + 480 + h * 8 + p] = sqrtf(nn);
    }
}

// ---------------- K5: output GEMM 768x384, K=2112, split-K=6 (f32x2) --------
__global__ __launch_bounds__(256) void k5_out(const float* __restrict__ out_w) {
    __shared__ float sA[32][65];
    __shared__ ull sB2[32][32];
    int tid = threadIdx.x, tx = tid & 15, ty = tid >> 4;
    int m0 = blockIdx.y * 64, n0 = blockIdx.x * 64;
    int kb = blockIdx.z * 352;
    ull acc[4][2] = {};
    for (int k0 = kb; k0 < kb + 352; k0 += 32) {
        for (int idx = tid; idx < 64 * 32; idx += 256) {
            int m = idx >> 5, kk = idx & 31;
            sA[kk][m] = g_final[(size_t)(m0 + m) * FINALD + k0 + kk];
        }
        for (int idx = tid; idx < 32 * 32; idx += 256) {
            int kk = idx >> 5, op = idx & 31;
            float2 wv = *(const float2*)(out_w + (size_t)(k0 + kk) * OUTD + n0 + op * 2);
            sB2[kk][op] = pk2two(wv.x, wv.y);
        }
        __syncthreads();
#pragma unroll
        for (int kk = 0; kk < 32; kk++) {
            ulonglong2 b01 = *(const ulonglong2*)&sB2[kk][tx * 2];
#pragma unroll
            for (int r = 0; r < 4; r++) {
                ull a2 = pk2(sA[kk][ty * 4 + r]);
                fma2(acc[r][0], a2, b01.x);
                fma2(acc[r][1], a2, b01.y);
            }
        }
        __syncthreads();
    }
#pragma unroll
    for (int r = 0; r < 4; r++) {
        int m = m0 + ty * 4 + r, o = n0 + tx * 4;
        float2 lo = upk(acc[r][0]), hi = upk(acc[r][1]);
        *(float4*)(g_part[blockIdx.z] + (size_t)m * OUTD + o) =
            make_float4(lo.x, lo.y, hi.x, hi.y);
    }
}

__global__ void k5r_reduce(const float* __restrict__ out_b, float* __restrict__ out) {
    int idx = blockIdx.x * 256 + threadIdx.x;
    if (idx < NRES * OUTD) {
        out[idx] = g_part[0][idx] + g_part[1][idx] + g_part[2][idx]
                 + g_part[3][idx] + g_part[4][idx] + g_part[5][idx] + out_b[idx % OUTD];
    }
}

// ---------------- launch: two-stream fork-join (graph-capturable) -----------
static cudaStream_t s_side = nullptr;
static cudaEvent_t ev_fork1 = nullptr, ev_join1 = nullptr;
static cudaEvent_t ev_fork2 = nullptr, ev_join2 = nullptr;

extern "C" void kernel_launch(void* const* d_in, const int* in_sizes, int n_in,
                              void* d_out, int out_size) {
    const float* in1d  = (const float*)d_in[0];
    const float* in2d  = (const float*)d_in[1];
    const float* rot   = (const float*)d_in[2];
    const float* trans = (const float*)d_in[3];
    const float* qw    = (const float*)d_in[4];
    const float* qb    = (const float*)d_in[5];
    const float* kvw   = (const float*)d_in[6];
    const float* kvb   = (const float*)d_in[7];
    const float* qpw   = (const float*)d_in[8];
    const float* qpb   = (const float*)d_in[9];
    const float* kvpw  = (const float*)d_in[10];
    const float* kvpb  = (const float*)d_in[11];
    const float* tpw   = (const float*)d_in[12];
    const float* w2d   = (const float*)d_in[13];
    const float* b2d   = (const float*)d_in[14];
    const float* ow    = (const float*)d_in[15];
    const float* ob    = (const float*)d_in[16];
    float* out = (float*)d_out;

    if (s_side == nullptr) {
        cudaStreamCreateWithFlags(&s_side, cudaStreamNonBlocking);
        cudaEventCreateWithFlags(&ev_fork1, cudaEventDisableTiming);
        cudaEventCreateWithFlags(&ev_join1, cudaEventDisableTiming);
        cudaEventCreateWithFlags(&ev_fork2, cudaEventDisableTiming);
        cudaEventCreateWithFlags(&ev_join2, cudaEventDisableTiming);
        cudaFuncSetAttribute(k2_a2d, cudaFuncAttributeMaxDynamicSharedMemorySize, K2_SMEM);
        cudaFuncSetAttribute(k4a_aover, cudaFuncAttributeMaxDynamicSharedMemorySize, K4A_SMEM);
    }

    // fork 1: side stream runs k1a->k1b while main stream runs k2
    cudaEventRecord(ev_fork1, 0);
    cudaStreamWaitEvent(s_side, ev_fork1, 0);
    k1a_gemm<<<dim3(18, 12), 256, 0, s_side>>>(in1d, qw, qb, kvw, kvb, qpw, qpb, kvpw, kvpb);
    k1b_pack<<<768, 256, 0, s_side>>>(rot, trans, tpw);
    cudaEventRecord(ev_join1, s_side);

    k2_a2d<<<4608, 128, K2_SMEM>>>(in2d, w2d, b2d);

    // join 1: k3 needs both k2 (a2d) and k1b (qpack/kpackT)
    cudaStreamWaitEvent(0, ev_join1, 0);
    k3_softmax<<<dim3(96, 12), 256>>>();

    // fork 2: side stream runs k4b while main runs k4a + k4r
    cudaEventRecord(ev_fork2, 0);
    cudaStreamWaitEvent(s_side, ev_fork2, 0);
    k4b_vattend<<<dim3(24, 12), 320, 0, s_side>>>(rot, trans);
    cudaEventRecord(ev_join2, s_side);

    k4a_aover<<<1536, 256, K4A_SMEM>>>(in2d);
    k4r_reduce<<<4608, 256>>>();

    // join 2: k5 needs g_final complete (k4r on main, k4b on side)
    cudaStreamWaitEvent(0, ev_join2, 0);
    k5_out<<<dim3(6, 12, 6), 256>>>(ow);
    k5r_reduce<<<1152, 256>>>(ob, out);
}